// round 1
// baseline (speedup 1.0000x reference)
#include <cuda_runtime.h>
#include <cuda_bf16.h>
#include <cstdint>

// ---------------------------------------------------------------------------
// PCA-whitening norm.
//   x: [N=64, C=64, H=128, W=128] fp32, weight[64], bias[64], v_init[32,64]
// Pipeline:
//   1. gram_kernel : partial Gram (x@x^T over columns) + per-channel sums
//   2. reduce_kernel: sum partials -> g_gram[4096], g_S[64]
//   3. eigen_kernel : cov -> 32x (10 power iters + Rayleigh + deflation)
//                     -> Wscaled = diag(weight) V^T diag(1/sqrt(lam+eps)) V
//                     -> off = bias - Wscaled @ mu
//   4. apply_kernel : out = Wscaled @ x + off
// ---------------------------------------------------------------------------

#define CCH   64
#define HWSZ  16384
#define NIMG  64
#define TC    128
#define RS    132            // smem tile row stride (floats)
#define NTILES 8192          // NIMG * HWSZ / TC
#define G1    296
#define G2    444
#define KEIG  32
#define EPSV  1e-5f

// scratch (no cudaMalloc allowed)
__device__ float g_pg[G1 * 4096];
__device__ float g_ps[G1 * 64];
__device__ float g_gram[4096];
__device__ float g_S[64];
__device__ float g_W[4096];
__device__ float g_off[64];

__device__ __forceinline__ void ffma2(unsigned long long& d,
                                      unsigned long long a,
                                      unsigned long long b) {
    asm("fma.rn.f32x2 %0, %1, %2, %0;" : "+l"(d) : "l"(a), "l"(b));
}
__device__ __forceinline__ unsigned long long pack2(float s) {
    unsigned long long d;
    asm("mov.b64 %0, {%1, %1};" : "=l"(d) : "f"(s));
    return d;
}
__device__ __forceinline__ void unpack2(unsigned long long d, float& lo, float& hi) {
    asm("mov.b64 {%0, %1}, %2;" : "=f"(lo), "=f"(hi) : "l"(d));
}

// ---------------------------------------------------------------------------
// Pass 1: partial Gram + channel sums.
// Block = 256 threads; smem tile [c][m] 64x128 (+pad). Two m-halves (g2),
// each 128-thread group does full 64x64 Gram with 8x4 register tiles, f32x2
// packed along m. Strided row/col fragment mapping keeps LDS conflicts <=2-way.
// ---------------------------------------------------------------------------
__global__ void __launch_bounds__(256, 2)
gram_kernel(const float* __restrict__ x) {
    __shared__ float tile[CCH * RS];
    const int t   = threadIdx.x;
    const int g2  = t >> 7;          // m-half: 0 or 1
    const int tg  = t & 127;
    const int i   = tg >> 4;         // rows i + 8r
    const int j   = tg & 15;         // cols j + 16c
    const int wa  = t >> 5;          // warp id -> channel group for loads
    const int lane = t & 31;
    const int mb  = g2 * 64;

    unsigned long long acc[8][4];
#pragma unroll
    for (int r = 0; r < 8; r++)
#pragma unroll
        for (int c = 0; c < 4; c++) acc[r][c] = 0ULL;
    float csum[8];
#pragma unroll
    for (int q = 0; q < 8; q++) csum[q] = 0.0f;

    for (int tau = blockIdx.x; tau < NTILES; tau += G1) {
        const int n  = tau >> 7;
        const int m0 = (tau & 127) << 7;
        const float* base = x + (size_t)(n * CCH) * HWSZ + m0;
#pragma unroll
        for (int q = 0; q < 8; q++) {
            const int c = q * 8 + wa;
            float4 v4 = *(const float4*)(base + (size_t)c * HWSZ + lane * 4);
            csum[q] += (v4.x + v4.y) + (v4.z + v4.w);
            *(float4*)(&tile[c * RS + lane * 4]) = v4;
        }
        __syncthreads();
#pragma unroll 4
        for (int mm = 0; mm < 64; mm += 2) {
            const int m = mb + mm;
            unsigned long long a2[8], b2[4];
#pragma unroll
            for (int r = 0; r < 8; r++)
                a2[r] = *(const unsigned long long*)(&tile[(i + 8 * r) * RS + m]);
#pragma unroll
            for (int c = 0; c < 4; c++)
                b2[c] = *(const unsigned long long*)(&tile[(j + 16 * c) * RS + m]);
#pragma unroll
            for (int r = 0; r < 8; r++)
#pragma unroll
                for (int c = 0; c < 4; c++) ffma2(acc[r][c], a2[r], b2[c]);
        }
        __syncthreads();
    }

    // per-channel sums: channel q*8+wa is fixed per (thread, q); warp-reduce
#pragma unroll
    for (int q = 0; q < 8; q++) {
        float s = csum[q];
#pragma unroll
        for (int off = 16; off > 0; off >>= 1)
            s += __shfl_down_sync(0xffffffffu, s, off);
        if (lane == 0) g_ps[blockIdx.x * 64 + q * 8 + wa] = s;
    }

    // combine the two m-halves in smem, then write coalesced partial gram
    if (g2 == 0) {
#pragma unroll
        for (int r = 0; r < 8; r++)
#pragma unroll
            for (int c = 0; c < 4; c++) {
                float lo, hi; unpack2(acc[r][c], lo, hi);
                tile[(i + 8 * r) * 65 + (j + 16 * c)] = lo + hi;
            }
    }
    __syncthreads();
    if (g2 == 1) {
#pragma unroll
        for (int r = 0; r < 8; r++)
#pragma unroll
            for (int c = 0; c < 4; c++) {
                float lo, hi; unpack2(acc[r][c], lo, hi);
                tile[(i + 8 * r) * 65 + (j + 16 * c)] += lo + hi;
            }
    }
    __syncthreads();
    float* pg = g_pg + (size_t)blockIdx.x * 4096;
#pragma unroll
    for (int kk = 0; kk < 16; kk++) {
        const int idx = t + kk * 256;
        pg[idx] = tile[(idx >> 6) * 65 + (idx & 63)];
    }
}

// ---------------------------------------------------------------------------
// Pass 1b: deterministic fixed-order reduction of partials.
// ---------------------------------------------------------------------------
__global__ void reduce_kernel() {
    const int b = blockIdx.x, t = threadIdx.x;
    if (b < 64) {
        const int idx = b * 64 + t;
        float s = 0.0f;
        for (int g = 0; g < G1; g++) s += g_pg[g * 4096 + idx];
        g_gram[idx] = s;
    } else {
        float s = 0.0f;
        for (int g = 0; g < G1; g++) s += g_ps[g * 64 + t];
        g_S[t] = s;
    }
}

// ---------------------------------------------------------------------------
// Eigen kernel: single block, 256 threads.
// cov = gram/M - mu mu^T + eps I ; 32x { v = normalize(cov^10 v0);
// lam = v^T cov v ; cov -= lam v v^T }.  Then Wscaled and offset.
// ---------------------------------------------------------------------------
__global__ void eigen_kernel(const float* __restrict__ weight,
                             const float* __restrict__ bias,
                             const float* __restrict__ vinit) {
    __shared__ float cov[64 * 65];
    __shared__ float v[64];
    __shared__ float wv[64];
    __shared__ float red[256];
    __shared__ float mu[64];
    __shared__ float Vs[KEIG * 64];
    __shared__ float lamArr[KEIG];
    __shared__ float invs[KEIG];
    __shared__ float scal;

    const int t = threadIdx.x;
    const float invM = 1.0f / 1048576.0f;

    if (t < 64) mu[t] = g_S[t] * invM;
    __syncthreads();
    for (int idx = t; idx < 4096; idx += 256) {
        const int ii = idx >> 6, jj = idx & 63;
        float c = g_gram[idx] * invM - mu[ii] * mu[jj];
        if (ii == jj) c += EPSV;
        cov[ii * 65 + jj] = c;
    }
    const int row = t & 63, part = t >> 6;
    __syncthreads();

    for (int k = 0; k < KEIG; k++) {
        if (t < 64) v[t] = vinit[k * 64 + t];
        __syncthreads();
        // 10 unnormalized power steps (normalization is scale-invariant)
        for (int it = 0; it < 10; it++) {
            float p = 0.0f;
#pragma unroll
            for (int q = 0; q < 16; q++)
                p += cov[row * 65 + part * 16 + q] * v[part * 16 + q];
            red[part * 64 + row] = p;
            __syncthreads();
            if (part == 0)
                v[row] = (red[row] + red[64 + row]) + (red[128 + row] + red[192 + row]);
            __syncthreads();
        }
        // normalize
        if (t < 64) red[t] = v[t] * v[t];
        __syncthreads();
        if (t < 32) {
            float s = red[t] + red[t + 32];
#pragma unroll
            for (int off = 16; off > 0; off >>= 1)
                s += __shfl_down_sync(0xffffffffu, s, off);
            if (t == 0) scal = 1.0f / sqrtf(s);
        }
        __syncthreads();
        if (t < 64) v[t] *= scal;
        __syncthreads();
        // wv = cov @ v ; lam = v . wv
        {
            float p = 0.0f;
#pragma unroll
            for (int q = 0; q < 16; q++)
                p += cov[row * 65 + part * 16 + q] * v[part * 16 + q];
            red[part * 64 + row] = p;
            __syncthreads();
            if (part == 0)
                wv[row] = (red[row] + red[64 + row]) + (red[128 + row] + red[192 + row]);
            __syncthreads();
        }
        if (t < 64) red[t] = v[t] * wv[t];
        __syncthreads();
        if (t < 32) {
            float s = red[t] + red[t + 32];
#pragma unroll
            for (int off = 16; off > 0; off >>= 1)
                s += __shfl_down_sync(0xffffffffu, s, off);
            if (t == 0) scal = s;
        }
        __syncthreads();
        const float lam = scal;
        if (t == 0) lamArr[k] = lam;
        if (t < 64) Vs[k * 64 + t] = v[t];
        __syncthreads();
        // deflate
        for (int idx = t; idx < 4096; idx += 256)
            cov[(idx >> 6) * 65 + (idx & 63)] -= lam * v[idx >> 6] * v[idx & 63];
        __syncthreads();
    }

    if (t < KEIG) invs[t] = 1.0f / sqrtf(lamArr[t] + EPSV);
    __syncthreads();
    for (int idx = t; idx < 4096; idx += 256) {
        const int c = idx >> 6, cp = idx & 63;
        float s = 0.0f;
#pragma unroll
        for (int k = 0; k < KEIG; k++)
            s += Vs[k * 64 + c] * invs[k] * Vs[k * 64 + cp];
        g_W[idx] = weight[c] * s;
    }
    __syncthreads();  // g_W writes visible within block
    if (t < 64) {
        float s = bias[t];
        for (int cp = 0; cp < 64; cp++) s -= g_W[t * 64 + cp] * mu[cp];
        g_off[t] = s;
    }
}

// ---------------------------------------------------------------------------
// Pass 2: out = Wscaled @ x + off, tiled like pass 1.
// Register tile 4 rows x 4 packed m-pairs per thread; W pre-packed (w,w) in
// smem (broadcast LDS.64), x pairs as conflict-free LDS.64.
// ---------------------------------------------------------------------------
#define APPLY_SMEM (CCH * RS * 4 + 4096 * 8 + 64 * 4)

__global__ void __launch_bounds__(256, 3)
apply_kernel(const float* __restrict__ x, float* __restrict__ out) {
    extern __shared__ float sm[];
    float* tile = sm;
    unsigned long long* sWp = (unsigned long long*)(sm + CCH * RS);
    float* soff = (float*)(sWp + 4096);

    const int t = threadIdx.x;
    for (int idx = t; idx < 4096; idx += 256) {
        // sWp[cp*64 + c] = pack2(W[c][cp])
        const float w = g_W[(idx & 63) * 64 + (idx >> 6)];
        sWp[idx] = pack2(w);
    }
    if (t < 64) soff[t] = g_off[t];

    const int wa = t >> 5, lane = t & 31;
    const int ic = t >> 4;          // rows ic + 16r
    const int jm = t & 15;          // m = 2*jm + 32p
    __syncthreads();

    for (int tau = blockIdx.x; tau < NTILES; tau += G2) {
        const int n  = tau >> 7;
        const int m0 = (tau & 127) << 7;
        const float* base = x + (size_t)(n * CCH) * HWSZ + m0;
#pragma unroll
        for (int q = 0; q < 8; q++) {
            const int c = q * 8 + wa;
            *(float4*)(&tile[c * RS + lane * 4]) =
                *(const float4*)(base + (size_t)c * HWSZ + lane * 4);
        }
        __syncthreads();

        unsigned long long acc[4][4];
#pragma unroll
        for (int r = 0; r < 4; r++) {
            const unsigned long long po = pack2(soff[ic + 16 * r]);
#pragma unroll
            for (int p = 0; p < 4; p++) acc[r][p] = po;
        }
#pragma unroll 4
        for (int cp = 0; cp < 64; cp++) {
            unsigned long long xv[4], wp[4];
#pragma unroll
            for (int p = 0; p < 4; p++)
                xv[p] = *(const unsigned long long*)(&tile[cp * RS + 2 * jm + 32 * p]);
#pragma unroll
            for (int r = 0; r < 4; r++)
                wp[r] = sWp[cp * 64 + ic + 16 * r];
#pragma unroll
            for (int r = 0; r < 4; r++)
#pragma unroll
                for (int p = 0; p < 4; p++) ffma2(acc[r][p], wp[r], xv[p]);
        }
        float* ob = out + (size_t)(n * CCH) * HWSZ + m0;
#pragma unroll
        for (int r = 0; r < 4; r++) {
            const int c = ic + 16 * r;
#pragma unroll
            for (int p = 0; p < 4; p++)
                *(unsigned long long*)(ob + (size_t)c * HWSZ + 2 * jm + 32 * p) = acc[r][p];
        }
        __syncthreads();
    }
}

// ---------------------------------------------------------------------------
extern "C" void kernel_launch(void* const* d_in, const int* in_sizes, int n_in,
                              void* d_out, int out_size) {
    const float* x      = (const float*)d_in[0];
    const float* weight = (const float*)d_in[1];
    const float* bias   = (const float*)d_in[2];
    const float* vinit  = (const float*)d_in[3];
    float* out = (float*)d_out;

    cudaFuncSetAttribute(apply_kernel,
                         cudaFuncAttributeMaxDynamicSharedMemorySize, APPLY_SMEM);

    gram_kernel<<<G1, 256>>>(x);
    reduce_kernel<<<65, 64>>>();
    eigen_kernel<<<1, 256>>>(weight, bias, vinit);
    apply_kernel<<<G2, 256, APPLY_SMEM>>>(x, out);
}